// round 2
// baseline (speedup 1.0000x reference)
#include <cuda_runtime.h>
#include <math.h>

#define DIMC 512
#define DIMK 128
#define HW   49
#define NSUP 25
#define NSAMP 26   // 25 supports + 1 query

// Scratch (allocation-free: __device__ globals)
__device__ float g_qq[HW * DIMK];          // [p][o]
__device__ float g_qv[HW * DIMK];          // [p][o]
__device__ float g_sk[NSUP * HW * DIMK];   // [s][p][o]
__device__ float g_sv[NSUP * HW * DIMK];   // [s][p][o]
__device__ float g_eu[NSUP * HW];          // per-(n,p) partial euclid sums

// ---------------------------------------------------------------------------
// Kernel A: fused projection GEMM.
//   For each sample s (25 supports + query) and each output row r in [0,256)
//   (rows 0..127 = W_qk, 128..255 = W_v):
//     out[r][p] = sum_c W[r][c] * X[s][c][p] * (s<25 ? 0.5 : 1.0)
//   Block = (sample, chunk of 64 rows). W chunk staged fully in smem
//   (512 x 64, pad 68), X staged in 4 K-tiles of 128 x 49 (pad 52).
//   Thread tile 4(rows) x 4(pos); 16 x 13 = 208 threads.
// ---------------------------------------------------------------------------
#define TPB_A 208
__global__ void __launch_bounds__(TPB_A)
kernelA(const float* __restrict__ query, const float* __restrict__ supports,
        const float* __restrict__ Wqk, const float* __restrict__ Wv)
{
    extern __shared__ float sm[];
    float* Ws = sm;              // [512][68]  (c-major, o padded to 68)
    float* Xs = sm + 512 * 68;   // [128][52]  (c-major, p padded to 52)

    const int s     = blockIdx.x;          // 0..25
    const int chunk = blockIdx.y;          // 0..3
    const float* X  = (s == NSUP) ? query : supports + (size_t)s * DIMC * HW;
    const float* W  = (chunk < 2) ? Wqk : Wv;
    const int row0  = (chunk & 1) * 64;

    const int tid = threadIdx.x;

    // Stage W chunk: 64 rows x 512 c  (coalesced global reads)
    for (int idx = tid; idx < 64 * DIMC; idx += TPB_A) {
        int c = idx & (DIMC - 1);
        int o = idx >> 9;
        Ws[c * 68 + o] = W[(row0 + o) * DIMC + c];
    }

    const int io = tid / 13;        // 0..15  -> rows io*4..io*4+3
    const int ip = tid - io * 13;   // 0..12  -> pos  ip*4..ip*4+3

    float acc[4][4] = {};

    for (int kt = 0; kt < 4; kt++) {
        __syncthreads();
        // Stage X tile: 128 c x 49 p, zero-pad p 49..51
        for (int idx = tid; idx < 128 * HW; idx += TPB_A) {
            int c = idx / HW;
            int p = idx - c * HW;
            Xs[c * 52 + p] = X[(kt * 128 + c) * HW + p];
        }
        for (int idx = tid; idx < 128 * 3; idx += TPB_A) {
            int c = idx / 3;
            Xs[c * 52 + 49 + (idx - c * 3)] = 0.f;
        }
        __syncthreads();

#pragma unroll 4
        for (int c = 0; c < 128; c++) {
            float4 w = *(const float4*)(Ws + (kt * 128 + c) * 68 + io * 4);
            float4 x = *(const float4*)(Xs + c * 52 + ip * 4);
            acc[0][0] += w.x * x.x; acc[0][1] += w.x * x.y; acc[0][2] += w.x * x.z; acc[0][3] += w.x * x.w;
            acc[1][0] += w.y * x.x; acc[1][1] += w.y * x.y; acc[1][2] += w.y * x.z; acc[1][3] += w.y * x.w;
            acc[2][0] += w.z * x.x; acc[2][1] += w.z * x.y; acc[2][2] += w.z * x.z; acc[2][3] += w.z * x.w;
            acc[3][0] += w.w * x.x; acc[3][1] += w.w * x.y; acc[3][2] += w.w * x.z; acc[3][3] += w.w * x.w;
        }
    }

    // Epilogue: supports get the analytic sigmoid factor 0.5 (see theory).
    const float scale = (s == NSUP) ? 1.0f : 0.5f;
    float* dq = (chunk < 2) ? g_qq : g_qv;
    float* ds = (chunk < 2) ? g_sk : g_sv;

#pragma unroll
    for (int j = 0; j < 4; j++) {
        int p = ip * 4 + j;
        if (p >= HW) continue;
#pragma unroll
        for (int i = 0; i < 4; i++) {
            int o = row0 + io * 4 + i;
            float v = acc[i][j] * scale;
            if (s == NSUP) dq[p * DIMK + o] = v;
            else           ds[((size_t)s * HW + p) * DIMK + o] = v;
        }
    }
}

// ---------------------------------------------------------------------------
// Kernel B: attention per (group n, query position p).
//   sims_j = (qq[:,p] . sk[s_j,:,ij_j]) * 128^-0.5, softmax over k*49 keys,
//   out_o  = sum_j attn_j * sv[s_j,o,ij_j],  partial = sum_o (qv[o,p]-out_o)^2
// ---------------------------------------------------------------------------
#define TPB_B 256
__global__ void __launch_bounds__(TPB_B)
kernelB(int k)
{
    const int ng = blockIdx.x;      // group index 0..n-1
    const int p  = blockIdx.y;      // query position 0..48
    const int nkeys = k * HW;       // 245 for n=5

    __shared__ float qqp[DIMK];
    __shared__ float sims[NSUP * HW + 7];
    __shared__ float outsh[DIMK];
    __shared__ float red[8];
    __shared__ float sM, sSum;

    const int tid = threadIdx.x;
    if (tid < DIMK) qqp[tid] = g_qq[p * DIMK + tid];
    __syncthreads();

    const float SCALE = 0.08838834764831845f;  // 128^-0.5

    // similarities
    for (int j = tid; j < nkeys; j += TPB_B) {
        int kk = j / HW;
        int ij = j - kk * HW;
        const float4* skv = (const float4*)(g_sk + (((size_t)(ng * k + kk)) * HW + ij) * DIMK);
        const float4* qv4 = (const float4*)qqp;
        float acc = 0.f;
#pragma unroll
        for (int o4 = 0; o4 < DIMK / 4; o4++) {
            float4 a = skv[o4];
            float4 b = qv4[o4];
            acc += a.x * b.x + a.y * b.y + a.z * b.z + a.w * b.w;
        }
        sims[j] = acc * SCALE;
    }
    __syncthreads();

    // softmax: block max
    float m = -1e30f;
    for (int j = tid; j < nkeys; j += TPB_B) m = fmaxf(m, sims[j]);
    for (int off = 16; off; off >>= 1) m = fmaxf(m, __shfl_xor_sync(~0u, m, off));
    if ((tid & 31) == 0) red[tid >> 5] = m;
    __syncthreads();
    if (tid < 8) {
        float v = red[tid];
        for (int off = 4; off; off >>= 1) v = fmaxf(v, __shfl_xor_sync(0xffu, v, off));
        if (tid == 0) sM = v;
    }
    __syncthreads();
    const float mv = sM;

    // exp + block sum
    float sum = 0.f;
    for (int j = tid; j < nkeys; j += TPB_B) {
        float e = __expf(sims[j] - mv);
        sims[j] = e;
        sum += e;
    }
    for (int off = 16; off; off >>= 1) sum += __shfl_xor_sync(~0u, sum, off);
    if ((tid & 31) == 0) red[tid >> 5] = sum;
    __syncthreads();
    if (tid < 8) {
        float v = red[tid];
        for (int off = 4; off; off >>= 1) v += __shfl_xor_sync(0xffu, v, off);
        if (tid == 0) sSum = v;
    }
    __syncthreads();
    const float inv = 1.f / sSum;

    // weighted value sum: 2 half-threads per channel o
    const int o = tid & 127;
    const int half = tid >> 7;
    float outo = 0.f;
    for (int j = half; j < nkeys; j += 2) {
        int kk = j / HW;
        int ij = j - kk * HW;
        outo += sims[j] * g_sv[(((size_t)(ng * k + kk)) * HW + ij) * DIMK + o];
    }
    if (half == 0) outsh[o] = outo;
    __syncthreads();
    if (half == 1) outsh[o] += outo;
    __syncthreads();

    // squared distance partial
    float e2 = 0.f;
    if (tid < DIMK) {
        float d = g_qv[p * DIMK + tid] - outsh[tid] * inv;
        e2 = d * d;
    }
    for (int off = 16; off; off >>= 1) e2 += __shfl_xor_sync(~0u, e2, off);
    if ((tid & 31) == 0) red[tid >> 5] = e2;
    __syncthreads();
    if (tid == 0) {
        float t = 0.f;
        for (int w = 0; w < 8; w++) t += red[w];
        g_eu[ng * HW + p] = t;
    }
}

// ---------------------------------------------------------------------------
// Kernel C: final reduction over 49 positions per group.
// ---------------------------------------------------------------------------
__global__ void kernelC(float* __restrict__ out)
{
    const int nn = blockIdx.x;
    const int tid = threadIdx.x;  // 64
    float s = 0.f;
    for (int pp = tid; pp < HW; pp += 64) s += g_eu[nn * HW + pp];
    for (int off = 16; off; off >>= 1) s += __shfl_xor_sync(~0u, s, off);
    __shared__ float r2[2];
    if ((tid & 31) == 0) r2[tid >> 5] = s;
    __syncthreads();
    if (tid == 0) out[nn] = -(r2[0] + r2[1]) / 49.0f;
}

// ---------------------------------------------------------------------------
extern "C" void kernel_launch(void* const* d_in, const int* in_sizes, int n_in,
                              void* d_out, int out_size)
{
    const float* query    = (const float*)d_in[0];   // (1,512,7,7)
    const float* supports = (const float*)d_in[1];   // (25,512,7,7)
    const float* Wqk      = (const float*)d_in[2];   // (128,512)
    const float* Wv       = (const float*)d_in[3];   // (128,512)
    float* out = (float*)d_out;

    int n = out_size;                 // output shape (1, n)
    if (n <= 0 || n > NSUP) n = 5;
    int k = NSUP / n;

    const size_t smemA = (size_t)(512 * 68 + 128 * 52) * sizeof(float);  // 165,888 B
    cudaFuncSetAttribute(kernelA, cudaFuncAttributeMaxDynamicSharedMemorySize, (int)smemA);

    dim3 gA(NSAMP, 4);
    kernelA<<<gA, TPB_A, smemA>>>(query, supports, Wqk, Wv);

    dim3 gB(n, HW);
    kernelB<<<gB, TPB_B>>>(k);

    kernelC<<<n, 64>>>(out);
}

// round 3
// speedup vs baseline: 1.4334x; 1.4334x over previous
#include <cuda_runtime.h>
#include <math.h>

#define DIMC 512
#define DIMK 128
#define HW   49
#define NSUP 25
#define NSAMP 26   // 25 supports + 1 query
#define NCOL (NSAMP * HW)   // 1274 output columns (s*49+p)

// Scratch (allocation-free: __device__ globals)
__device__ float g_part[4 * NCOL * 256];   // split-K partials [ks][n][m]
__device__ float g_qq[HW * DIMK];          // [p][o]
__device__ float g_qv[HW * DIMK];          // [p][o]
__device__ float g_sk[NSUP * HW * DIMK];   // [s][p][o]
__device__ float g_sv[NSUP * HW * DIMK];   // [s][p][o]
__device__ float g_eu[NSUP * HW];          // per-(n,p) partial euclid sums

// ---- packed fp32x2 helpers (sm_10x) --------------------------------------
__device__ __forceinline__ unsigned long long pack2(float a, float b) {
    unsigned long long r;
    asm("mov.b64 %0, {%1, %2};" : "=l"(r) : "f"(a), "f"(b));
    return r;
}
__device__ __forceinline__ void fma2(unsigned long long& d,
                                     unsigned long long a, unsigned long long b) {
    asm("fma.rn.f32x2 %0, %1, %2, %0;" : "+l"(d) : "l"(a), "l"(b));
}
__device__ __forceinline__ float2 unpack2(unsigned long long v) {
    float2 f;
    asm("mov.b64 {%0, %1}, %2;" : "=f"(f.x), "=f"(f.y) : "l"(v));
    return f;
}

// ---------------------------------------------------------------------------
// Kernel A: split-K projection GEMM.
//   C[m][n] = sum_c W[m][c] * X[c][n],  m in [0,256) (128 Wqk rows + 128 Wv),
//   n = s*49 + p over 26 samples. Block = (sample, m-tile of 64, k-chunk of
//   128). Partial written to g_part[ks]. W staged m-major (conflict-free),
//   X staged c-major; inner loop: w scalar broadcast x packed-f32x2 vector.
//   208 threads = 16 io x 13 ip, thread tile 4 rows x 4 positions.
// ---------------------------------------------------------------------------
#define TPB_A 208
#define WPITCH 132
#define XPITCH 52
__global__ void __launch_bounds__(TPB_A)
kernelA(const float* __restrict__ query, const float* __restrict__ supports,
        const float* __restrict__ Wqk, const float* __restrict__ Wv)
{
    extern __shared__ float sm[];
    float* Ws = sm;                    // [64][132]  (m-major, c padded)
    float* Xs = sm + 64 * WPITCH;      // [128][52]  (c-major, p padded)

    const int s  = blockIdx.x;         // sample 0..25
    const int mt = blockIdx.y;         // m-tile 0..3
    const int ks = blockIdx.z;         // k-chunk 0..3
    const int c0 = ks * 128;
    const float* W    = (mt < 2) ? Wqk : Wv;
    const int wrow0   = (mt & 1) * 64;
    const float* X    = (s == NSUP) ? query : supports + (size_t)s * DIMC * HW;

    const int tid = threadIdx.x;

    // Stage W tile: 64 rows x 128 c, m-major (writes contiguous along c)
    for (int idx = tid; idx < 64 * 128; idx += TPB_A) {
        int o = idx >> 7, c = idx & 127;
        Ws[o * WPITCH + c] = W[(wrow0 + o) * DIMC + c0 + c];
    }
    // Stage X tile: 128 c x 49 p (coalesced), zero-pad p 49..51
    for (int idx = tid; idx < 128 * HW; idx += TPB_A) {
        int c = idx / HW, p = idx - c * HW;
        Xs[c * XPITCH + p] = X[(c0 + c) * HW + p];
    }
    for (int idx = tid; idx < 128 * 3; idx += TPB_A) {
        int c = idx / 3;
        Xs[c * XPITCH + HW + (idx - c * 3)] = 0.f;
    }
    __syncthreads();

    const int io = tid / 13;         // 0..15 -> rows io*4..io*4+3
    const int ip = tid - io * 13;    // 0..12 -> pos  ip*4..ip*4+3

    unsigned long long acc[4][2] = {};

    const float* wbase = Ws + io * 4 * WPITCH;
    const float* xbase = Xs + ip * 4;

#pragma unroll 8
    for (int c4 = 0; c4 < 32; c4++) {
        // w for 4 rows x 4 consecutive c (vector loads along c, m-major)
        float4 w0 = *(const float4*)(wbase + 0 * WPITCH + c4 * 4);
        float4 w1 = *(const float4*)(wbase + 1 * WPITCH + c4 * 4);
        float4 w2 = *(const float4*)(wbase + 2 * WPITCH + c4 * 4);
        float4 w3 = *(const float4*)(wbase + 3 * WPITCH + c4 * 4);
#pragma unroll
        for (int cc = 0; cc < 4; cc++) {
            const ulonglong2 xv =
                *(const ulonglong2*)(xbase + (c4 * 4 + cc) * XPITCH);
            float e0 = (cc == 0) ? w0.x : (cc == 1) ? w0.y : (cc == 2) ? w0.z : w0.w;
            float e1 = (cc == 0) ? w1.x : (cc == 1) ? w1.y : (cc == 2) ? w1.z : w1.w;
            float e2 = (cc == 0) ? w2.x : (cc == 1) ? w2.y : (cc == 2) ? w2.z : w2.w;
            float e3 = (cc == 0) ? w3.x : (cc == 1) ? w3.y : (cc == 2) ? w3.z : w3.w;
            unsigned long long d0 = pack2(e0, e0);
            unsigned long long d1 = pack2(e1, e1);
            unsigned long long d2 = pack2(e2, e2);
            unsigned long long d3 = pack2(e3, e3);
            fma2(acc[0][0], d0, xv.x);  fma2(acc[0][1], d0, xv.y);
            fma2(acc[1][0], d1, xv.x);  fma2(acc[1][1], d1, xv.y);
            fma2(acc[2][0], d2, xv.x);  fma2(acc[2][1], d2, xv.y);
            fma2(acc[3][0], d3, xv.x);  fma2(acc[3][1], d3, xv.y);
        }
    }

    // Epilogue: write partial tile
    float* base = g_part + (size_t)ks * (NCOL * 256);
    const int m0 = mt * 64 + io * 4;
#pragma unroll
    for (int i = 0; i < 4; i++) {
        float2 lo = unpack2(acc[i][0]);
        float2 hi = unpack2(acc[i][1]);
        float v[4] = {lo.x, lo.y, hi.x, hi.y};
#pragma unroll
        for (int j = 0; j < 4; j++) {
            int p = ip * 4 + j;
            if (p < HW) base[(s * HW + p) * 256 + m0 + i] = v[j];
        }
    }
}

// ---------------------------------------------------------------------------
// Kernel R: reduce split-K partials, apply analytic sigmoid factor (0.5 for
// supports — see round-1 theory), scatter into attention layouts.
// ---------------------------------------------------------------------------
__global__ void __launch_bounds__(256)
kernelR()
{
    const int idx = blockIdx.x * 256 + threadIdx.x;   // grid 1274 x 256
    const int m = idx & 255;
    const int n = idx >> 8;
    const int s = n / HW;
    const int p = n - s * HW;

    float v = g_part[idx]
            + g_part[1 * NCOL * 256 + idx]
            + g_part[2 * NCOL * 256 + idx]
            + g_part[3 * NCOL * 256 + idx];

    const int o = m & 127;
    if (s == NSUP) {
        if (m < 128) g_qq[p * DIMK + o] = v;
        else         g_qv[p * DIMK + o] = v;
    } else {
        v *= 0.5f;
        if (m < 128) g_sk[((size_t)s * HW + p) * DIMK + o] = v;
        else         g_sv[((size_t)s * HW + p) * DIMK + o] = v;
    }
}

// ---------------------------------------------------------------------------
// Kernel B: attention per (group n, query position p).  (unchanged — ~1us)
// ---------------------------------------------------------------------------
#define TPB_B 256
__global__ void __launch_bounds__(TPB_B)
kernelB(int k)
{
    const int ng = blockIdx.x;
    const int p  = blockIdx.y;
    const int nkeys = k * HW;

    __shared__ float qqp[DIMK];
    __shared__ float sims[NSUP * HW + 7];
    __shared__ float outsh[DIMK];
    __shared__ float red[8];
    __shared__ float sM, sSum;

    const int tid = threadIdx.x;
    if (tid < DIMK) qqp[tid] = g_qq[p * DIMK + tid];
    __syncthreads();

    const float SCALE = 0.08838834764831845f;  // 128^-0.5

    for (int j = tid; j < nkeys; j += TPB_B) {
        int kk = j / HW;
        int ij = j - kk * HW;
        const float4* skv = (const float4*)(g_sk + (((size_t)(ng * k + kk)) * HW + ij) * DIMK);
        const float4* qv4 = (const float4*)qqp;
        float acc = 0.f;
#pragma unroll
        for (int o4 = 0; o4 < DIMK / 4; o4++) {
            float4 a = skv[o4];
            float4 b = qv4[o4];
            acc += a.x * b.x + a.y * b.y + a.z * b.z + a.w * b.w;
        }
        sims[j] = acc * SCALE;
    }
    __syncthreads();

    float m = -1e30f;
    for (int j = tid; j < nkeys; j += TPB_B) m = fmaxf(m, sims[j]);
    for (int off = 16; off; off >>= 1) m = fmaxf(m, __shfl_xor_sync(~0u, m, off));
    if ((tid & 31) == 0) red[tid >> 5] = m;
    __syncthreads();
    if (tid < 8) {
        float v = red[tid];
        for (int off = 4; off; off >>= 1) v = fmaxf(v, __shfl_xor_sync(0xffu, v, off));
        if (tid == 0) sM = v;
    }
    __syncthreads();
    const float mv = sM;

    float sum = 0.f;
    for (int j = tid; j < nkeys; j += TPB_B) {
        float e = __expf(sims[j] - mv);
        sims[j] = e;
        sum += e;
    }
    for (int off = 16; off; off >>= 1) sum += __shfl_xor_sync(~0u, sum, off);
    if ((tid & 31) == 0) red[tid >> 5] = sum;
    __syncthreads();
    if (tid < 8) {
        float v = red[tid];
        for (int off = 4; off; off >>= 1) v += __shfl_xor_sync(0xffu, v, off);
        if (tid == 0) sSum = v;
    }
    __syncthreads();
    const float inv = 1.f / sSum;

    const int o = tid & 127;
    const int half = tid >> 7;
    float outo = 0.f;
    for (int j = half; j < nkeys; j += 2) {
        int kk = j / HW;
        int ij = j - kk * HW;
        outo += sims[j] * g_sv[(((size_t)(ng * k + kk)) * HW + ij) * DIMK + o];
    }
    if (half == 0) outsh[o] = outo;
    __syncthreads();
    if (half == 1) outsh[o] += outo;
    __syncthreads();

    float e2 = 0.f;
    if (tid < DIMK) {
        float d = g_qv[p * DIMK + tid] - outsh[tid] * inv;
        e2 = d * d;
    }
    for (int off = 16; off; off >>= 1) e2 += __shfl_xor_sync(~0u, e2, off);
    if ((tid & 31) == 0) red[tid >> 5] = e2;
    __syncthreads();
    if (tid == 0) {
        float t = 0.f;
        for (int w = 0; w < 8; w++) t += red[w];
        g_eu[ng * HW + p] = t;
    }
}

// ---------------------------------------------------------------------------
// Kernel C: final reduction over 49 positions per group.
// ---------------------------------------------------------------------------
__global__ void kernelC(float* __restrict__ out)
{
    const int nn = blockIdx.x;
    const int tid = threadIdx.x;  // 64
    float s = 0.f;
    for (int pp = tid; pp < HW; pp += 64) s += g_eu[nn * HW + pp];
    for (int off = 16; off; off >>= 1) s += __shfl_xor_sync(~0u, s, off);
    __shared__ float r2[2];
    if ((tid & 31) == 0) r2[tid >> 5] = s;
    __syncthreads();
    if (tid == 0) out[nn] = -(r2[0] + r2[1]) / 49.0f;
}

// ---------------------------------------------------------------------------
extern "C" void kernel_launch(void* const* d_in, const int* in_sizes, int n_in,
                              void* d_out, int out_size)
{
    const float* query    = (const float*)d_in[0];   // (1,512,7,7)
    const float* supports = (const float*)d_in[1];   // (25,512,7,7)
    const float* Wqk      = (const float*)d_in[2];   // (128,512)
    const float* Wv       = (const float*)d_in[3];   // (128,512)
    float* out = (float*)d_out;

    int n = out_size;                 // output shape (1, n)
    if (n <= 0 || n > NSUP) n = 5;
    int k = NSUP / n;

    const size_t smemA = (size_t)(64 * WPITCH + 128 * XPITCH) * sizeof(float); // 60,416 B
    static int attrSet = 0;
    cudaFuncSetAttribute(kernelA, cudaFuncAttributeMaxDynamicSharedMemorySize, (int)smemA);
    (void)attrSet;

    dim3 gA(NSAMP, 4, 4);
    kernelA<<<gA, TPB_A, smemA>>>(query, supports, Wqk, Wv);

    kernelR<<<NCOL, 256>>>();

    dim3 gB(n, HW);
    kernelB<<<gB, TPB_B>>>(k);

    kernelC<<<n, 64>>>(out);
}